// round 11
// baseline (speedup 1.0000x reference)
#include <cuda_runtime.h>
#include <math.h>
#include <stdint.h>

// Problem constants
#define B   16
#define N   1024
#define H   256
#define DS  3
#define HEADS 8
#define DH  32
#define TWO_H 512
#define M_ROWS (B * N)          // 16384
#define EPS 1e-5f
#define SCALE 0.17677669529663687f  // 1/sqrt(32)

// ---------------- scratch (static device globals; no allocation) -------------
__device__ float g_f  [M_ROWS * TWO_H];
__device__ float g_q  [M_ROWS * H];
__device__ float g_k  [M_ROWS * H];
__device__ float g_v  [M_ROWS * H];
__device__ float g_msg[M_ROWS * H];
__device__ float g_m  [M_ROWS * H];

// ---------------- tf32 helpers ------------------------------------------------
__device__ __forceinline__ uint32_t f2tf32(float f) {
    uint32_t u;
    asm("cvt.rna.tf32.f32 %0, %1;" : "=r"(u) : "f"(f));
    return u;
}

__device__ __forceinline__ void mma_tf32(float* c,
                                         uint32_t a0, uint32_t a1, uint32_t a2, uint32_t a3,
                                         uint32_t b0, uint32_t b1) {
    asm volatile(
        "mma.sync.aligned.m16n8k8.row.col.f32.tf32.tf32.f32 "
        "{%0,%1,%2,%3}, {%4,%5,%6,%7}, {%8,%9}, {%0,%1,%2,%3};\n"
        : "+f"(c[0]), "+f"(c[1]), "+f"(c[2]), "+f"(c[3])
        : "r"(a0), "r"(a1), "r"(a2), "r"(a3), "r"(b0), "r"(b1));
}

// ---------------- kernel 1: dual LayerNorm + concat (one-pass, shfl) ---------
__global__ void ln_concat_kernel(const float* __restrict__ xs,
                                 const float* __restrict__ xo,
                                 const float* __restrict__ gs,
                                 const float* __restrict__ bs,
                                 const float* __restrict__ go,
                                 const float* __restrict__ bo) {
    __shared__ float red[8][4];
    __shared__ float res[4];
    int row = blockIdx.x;
    int t = threadIdx.x;
    int lane = t & 31, warp = t >> 5;

    float v1 = xs[row * H + t];
    float v2 = xo[row * H + t];

    float s1 = v1, q1 = v1 * v1, s2 = v2, q2 = v2 * v2;
    #pragma unroll
    for (int off = 16; off > 0; off >>= 1) {
        s1 += __shfl_xor_sync(0xFFFFFFFFu, s1, off);
        q1 += __shfl_xor_sync(0xFFFFFFFFu, q1, off);
        s2 += __shfl_xor_sync(0xFFFFFFFFu, s2, off);
        q2 += __shfl_xor_sync(0xFFFFFFFFu, q2, off);
    }
    if (lane == 0) {
        red[warp][0] = s1; red[warp][1] = q1;
        red[warp][2] = s2; red[warp][3] = q2;
    }
    __syncthreads();
    if (t < 32) {
        int q = t >> 3, w = t & 7;
        float x = red[w][q];
        x += __shfl_xor_sync(0xFFFFFFFFu, x, 1);
        x += __shfl_xor_sync(0xFFFFFFFFu, x, 2);
        x += __shfl_xor_sync(0xFFFFFFFFu, x, 4);
        if (w == 0) res[q] = x;
    }
    __syncthreads();

    float mean1 = res[0] * (1.0f / H);
    float var1  = res[1] * (1.0f / H) - mean1 * mean1;
    float mean2 = res[2] * (1.0f / H);
    float var2  = res[3] * (1.0f / H) - mean2 * mean2;

    g_f[row * TWO_H + t]     = (v1 - mean1) * rsqrtf(var1 + EPS) * gs[t] + bs[t];
    g_f[row * TWO_H + H + t] = (v2 - mean2) * rsqrtf(var2 + EPS) * go[t] + bo[t];
}

// ---------------- tf32 MMA GEMM with register-staged prefetch -----------------
// C[M,256] = A[M,K] @ W[K,256]; 128x64 tile, 8 warps (4m x 2n), warp 32x32
__device__ __forceinline__ void gemm_mma_body(const float* __restrict__ A,
                                              const float* __restrict__ W,
                                              float* __restrict__ C,
                                              int K, int row0, int col0) {
    __shared__ uint32_t As[128][36];
    __shared__ uint32_t Bs[32][72];

    int t = threadIdx.x;
    int w = t >> 5, lane = t & 31;
    int quad = lane >> 2, c = lane & 3;
    int wm = (w & 3) * 32;
    int wn = (w >> 2) * 32;

    float acc[2][4][4];
    #pragma unroll
    for (int mt = 0; mt < 2; mt++)
        #pragma unroll
        for (int nt = 0; nt < 4; nt++)
            #pragma unroll
            for (int i = 0; i < 4; i++) acc[mt][nt][i] = 0.0f;

    int a_row = t >> 1, a_col = (t & 1) * 16;
    int b_row = t >> 3, b_col = (t & 7) * 8;

    // prefetch first k-tile into registers
    float4 f0, f1, f2, f3, gg0, gg1;
    {
        const float* ap = A + (size_t)(row0 + a_row) * K + a_col;
        f0 = *(const float4*)(ap + 0);
        f1 = *(const float4*)(ap + 4);
        f2 = *(const float4*)(ap + 8);
        f3 = *(const float4*)(ap + 12);
        const float* bp = W + (size_t)b_row * H + col0 + b_col;
        gg0 = *(const float4*)(bp + 0);
        gg1 = *(const float4*)(bp + 4);
    }

    for (int k0 = 0; k0 < K; k0 += 32) {
        // store staged tile to smem (tf32)
        uint4 u;
        u.x = f2tf32(f0.x); u.y = f2tf32(f0.y); u.z = f2tf32(f0.z); u.w = f2tf32(f0.w);
        *(uint4*)&As[a_row][a_col + 0] = u;
        u.x = f2tf32(f1.x); u.y = f2tf32(f1.y); u.z = f2tf32(f1.z); u.w = f2tf32(f1.w);
        *(uint4*)&As[a_row][a_col + 4] = u;
        u.x = f2tf32(f2.x); u.y = f2tf32(f2.y); u.z = f2tf32(f2.z); u.w = f2tf32(f2.w);
        *(uint4*)&As[a_row][a_col + 8] = u;
        u.x = f2tf32(f3.x); u.y = f2tf32(f3.y); u.z = f2tf32(f3.z); u.w = f2tf32(f3.w);
        *(uint4*)&As[a_row][a_col + 12] = u;
        u.x = f2tf32(gg0.x); u.y = f2tf32(gg0.y); u.z = f2tf32(gg0.z); u.w = f2tf32(gg0.w);
        *(uint4*)&Bs[b_row][b_col + 0] = u;
        u.x = f2tf32(gg1.x); u.y = f2tf32(gg1.y); u.z = f2tf32(gg1.z); u.w = f2tf32(gg1.w);
        *(uint4*)&Bs[b_row][b_col + 4] = u;
        __syncthreads();

        // issue next tile's global loads (overlap with MMA below)
        if (k0 + 32 < K) {
            const float* ap = A + (size_t)(row0 + a_row) * K + k0 + 32 + a_col;
            f0 = *(const float4*)(ap + 0);
            f1 = *(const float4*)(ap + 4);
            f2 = *(const float4*)(ap + 8);
            f3 = *(const float4*)(ap + 12);
            const float* bp = W + (size_t)(k0 + 32 + b_row) * H + col0 + b_col;
            gg0 = *(const float4*)(bp + 0);
            gg1 = *(const float4*)(bp + 4);
        }

        #pragma unroll
        for (int ks = 0; ks < 4; ks++) {
            int kk = ks * 8;
            uint32_t a[2][4];
            #pragma unroll
            for (int mt = 0; mt < 2; mt++) {
                int mrow = wm + mt * 16;
                a[mt][0] = As[mrow + quad][kk + c];
                a[mt][1] = As[mrow + quad + 8][kk + c];
                a[mt][2] = As[mrow + quad][kk + c + 4];
                a[mt][3] = As[mrow + quad + 8][kk + c + 4];
            }
            #pragma unroll
            for (int nt = 0; nt < 4; nt++) {
                uint32_t b0 = Bs[kk + c][wn + nt * 8 + quad];
                uint32_t b1 = Bs[kk + c + 4][wn + nt * 8 + quad];
                #pragma unroll
                for (int mt = 0; mt < 2; mt++)
                    mma_tf32(acc[mt][nt], a[mt][0], a[mt][1], a[mt][2], a[mt][3], b0, b1);
            }
        }
        __syncthreads();
    }

    #pragma unroll
    for (int mt = 0; mt < 2; mt++) {
        int row = row0 + wm + mt * 16 + quad;
        #pragma unroll
        for (int nt = 0; nt < 4; nt++) {
            int col = col0 + wn + nt * 8 + 2 * c;
            *(float2*)&C[(size_t)row * H + col] = make_float2(acc[mt][nt][0], acc[mt][nt][1]);
            *(float2*)&C[(size_t)(row + 8) * H + col] = make_float2(acc[mt][nt][2], acc[mt][nt][3]);
        }
    }
}

__global__ void __launch_bounds__(256)
qkv_gemm_kernel(const float* __restrict__ Wq,
                const float* __restrict__ Wk,
                const float* __restrict__ Wv) {
    int sel = blockIdx.y >> 2;
    const float* W = (sel == 0) ? Wq : (sel == 1) ? Wk : Wv;
    float* C = (sel == 0) ? g_q : (sel == 1) ? g_k : g_v;
    gemm_mma_body(g_f, W, C, TWO_H, blockIdx.x * 128, (blockIdx.y & 3) * 64);
}

__global__ void __launch_bounds__(256)
wo_gemm_kernel(const float* __restrict__ Wo) {
    gemm_mma_body(g_msg, Wo, g_m, H, blockIdx.x * 128, blockIdx.y * 64);
}

// ---------------- attention (tf32 mma, no-max softmax, prefetch) ---------------
// grid (N/256, HEADS, B), 256 threads = 8 warps; warp w -> 32 q rows (2 m-tiles)
__global__ void __launch_bounds__(256)
attn_kernel() {
    __shared__ uint32_t Ks[128][36];
    __shared__ uint32_t Vs[128][40];

    int b = blockIdx.z;
    int h = blockIdx.y;
    int q0 = blockIdx.x * 256;
    int t = threadIdx.x;
    int w = t >> 5, lane = t & 31;
    int quad = lane >> 2;
    int c    = lane & 3;
    int base = lane & ~3;
    int src1 = base | (c >> 1);
    int src2 = base | ((c >> 1) + 2);
    bool odd = (c & 1);

    // Q fragments for 2 m-tiles (rows w*32 + mt*16 + {quad, quad+8})
    uint32_t qa[2][4][4];
    #pragma unroll
    for (int mt = 0; mt < 2; mt++) {
        const float* qb  = g_q + (size_t)(b * N + q0 + w * 32 + mt * 16 + quad) * H + h * DH;
        const float* qb8 = qb + 8 * H;
        #pragma unroll
        for (int ks = 0; ks < 4; ks++) {
            qa[mt][ks][0] = f2tf32(qb [ks * 8 + c]     * SCALE);
            qa[mt][ks][1] = f2tf32(qb8[ks * 8 + c]     * SCALE);
            qa[mt][ks][2] = f2tf32(qb [ks * 8 + c + 4] * SCALE);
            qa[mt][ks][3] = f2tf32(qb8[ks * 8 + c + 4] * SCALE);
        }
    }

    float o[2][4][4];
    #pragma unroll
    for (int mt = 0; mt < 2; mt++)
        #pragma unroll
        for (int nt = 0; nt < 4; nt++)
            #pragma unroll
            for (int i = 0; i < 4; i++) o[mt][nt][i] = 0.0f;
    float lsum[2][2] = {{0.0f, 0.0f}, {0.0f, 0.0f}};

    // staging registers for K/V tile (4 float4 each)
    float4 kf[4], vf[4];
    int st_row[4], st_d4[4];
    #pragma unroll
    for (int it = 0; it < 4; it++) {
        int idx = it * 256 + t;
        st_row[it] = idx >> 3;
        st_d4[it]  = (idx & 7) * 4;
        size_t gbase = (size_t)(b * N + st_row[it]) * H + h * DH + st_d4[it];
        kf[it] = *(const float4*)&g_k[gbase];
        vf[it] = *(const float4*)&g_v[gbase];
    }

    for (int j0t = 0; j0t < N; j0t += 128) {
        // store staged tile (tf32)
        #pragma unroll
        for (int it = 0; it < 4; it++) {
            uint4 ku, vu;
            ku.x = f2tf32(kf[it].x); ku.y = f2tf32(kf[it].y);
            ku.z = f2tf32(kf[it].z); ku.w = f2tf32(kf[it].w);
            vu.x = f2tf32(vf[it].x); vu.y = f2tf32(vf[it].y);
            vu.z = f2tf32(vf[it].z); vu.w = f2tf32(vf[it].w);
            *(uint4*)&Ks[st_row[it]][st_d4[it]] = ku;
            *(uint4*)&Vs[st_row[it]][st_d4[it]] = vu;
        }
        __syncthreads();

        // issue next tile's loads (overlap with compute)
        if (j0t + 128 < N) {
            #pragma unroll
            for (int it = 0; it < 4; it++) {
                size_t gbase = (size_t)(b * N + j0t + 128 + st_row[it]) * H + h * DH + st_d4[it];
                kf[it] = *(const float4*)&g_k[gbase];
                vf[it] = *(const float4*)&g_v[gbase];
            }
        }

        #pragma unroll 2
        for (int nb = 0; nb < 16; nb++) {
            int j0 = nb * 8;
            float s[2][4] = {{0,0,0,0},{0,0,0,0}};
            #pragma unroll
            for (int ks = 0; ks < 4; ks++) {
                uint32_t b0 = Ks[j0 + quad][ks * 8 + c];
                uint32_t b1 = Ks[j0 + quad][ks * 8 + c + 4];
                mma_tf32(s[0], qa[0][ks][0], qa[0][ks][1], qa[0][ks][2], qa[0][ks][3], b0, b1);
                mma_tf32(s[1], qa[1][ks][0], qa[1][ks][1], qa[1][ks][2], qa[1][ks][3], b0, b1);
            }
            uint32_t pa[2][4];
            #pragma unroll
            for (int mt = 0; mt < 2; mt++) {
                float p0 = __expf(s[mt][0]), p1 = __expf(s[mt][1]);
                float p2 = __expf(s[mt][2]), p3 = __expf(s[mt][3]);
                lsum[mt][0] += p0 + p1;
                lsum[mt][1] += p2 + p3;
                uint32_t t0 = f2tf32(p0), t1 = f2tf32(p1);
                uint32_t t2 = f2tf32(p2), t3 = f2tf32(p3);
                uint32_t u0 = __shfl_sync(0xFFFFFFFFu, t0, src1);
                uint32_t u1 = __shfl_sync(0xFFFFFFFFu, t1, src1);
                uint32_t w0 = __shfl_sync(0xFFFFFFFFu, t2, src1);
                uint32_t w1 = __shfl_sync(0xFFFFFFFFu, t3, src1);
                uint32_t v0 = __shfl_sync(0xFFFFFFFFu, t0, src2);
                uint32_t v1 = __shfl_sync(0xFFFFFFFFu, t1, src2);
                uint32_t x0 = __shfl_sync(0xFFFFFFFFu, t2, src2);
                uint32_t x1 = __shfl_sync(0xFFFFFFFFu, t3, src2);
                pa[mt][0] = odd ? u1 : u0;
                pa[mt][1] = odd ? w1 : w0;
                pa[mt][2] = odd ? v1 : v0;
                pa[mt][3] = odd ? x1 : x0;
            }
            #pragma unroll
            for (int nt = 0; nt < 4; nt++) {
                uint32_t b0 = Vs[j0 + c][nt * 8 + quad];
                uint32_t b1 = Vs[j0 + c + 4][nt * 8 + quad];
                mma_tf32(o[0][nt], pa[0][0], pa[0][1], pa[0][2], pa[0][3], b0, b1);
                mma_tf32(o[1][nt], pa[1][0], pa[1][1], pa[1][2], pa[1][3], b0, b1);
            }
        }
        __syncthreads();
    }

    #pragma unroll
    for (int mt = 0; mt < 2; mt++) {
        float l0 = lsum[mt][0], l1 = lsum[mt][1];
        l0 += __shfl_xor_sync(0xFFFFFFFFu, l0, 1);
        l0 += __shfl_xor_sync(0xFFFFFFFFu, l0, 2);
        l1 += __shfl_xor_sync(0xFFFFFFFFu, l1, 1);
        l1 += __shfl_xor_sync(0xFFFFFFFFu, l1, 2);
        float inv0 = 1.0f / l0, inv1 = 1.0f / l1;

        float* ob  = g_msg + (size_t)(b * N + q0 + w * 32 + mt * 16 + quad) * H + h * DH;
        float* ob8 = ob + 8 * H;
        #pragma unroll
        for (int nt = 0; nt < 4; nt++) {
            int col = nt * 8 + 2 * c;
            *(float2*)&ob [col] = make_float2(o[mt][nt][0] * inv0, o[mt][nt][1] * inv0);
            *(float2*)&ob8[col] = make_float2(o[mt][nt][2] * inv1, o[mt][nt][3] * inv1);
        }
    }
}

// ---------------- kernel 5: residual + position head -------------------------
__global__ void finish_kernel(const float* __restrict__ x_out,
                              const float* __restrict__ Wp,
                              float* __restrict__ out_x,
                              float* __restrict__ out_p) {
    int warp = threadIdx.x >> 5;
    int lane = threadIdx.x & 31;
    int row = blockIdx.x * 8 + warp;

    const float* mr = g_m + (size_t)row * H;
    float p0 = 0.0f, p1 = 0.0f, p2 = 0.0f;
    #pragma unroll
    for (int c = lane; c < H; c += 32) {
        float mv = mr[c];
        out_x[(size_t)row * H + c] = x_out[(size_t)row * H + c] + mv;
        p0 += mv * Wp[c * DS + 0];
        p1 += mv * Wp[c * DS + 1];
        p2 += mv * Wp[c * DS + 2];
    }
    #pragma unroll
    for (int off = 16; off > 0; off >>= 1) {
        p0 += __shfl_xor_sync(0xFFFFFFFF, p0, off);
        p1 += __shfl_xor_sync(0xFFFFFFFF, p1, off);
        p2 += __shfl_xor_sync(0xFFFFFFFF, p2, off);
    }
    if (lane == 0) {
        out_p[(size_t)row * DS + 0] = p0;
        out_p[(size_t)row * DS + 1] = p1;
        out_p[(size_t)row * DS + 2] = p2;
    }
}

// ---------------- launcher ----------------------------------------------------
extern "C" void kernel_launch(void* const* d_in, const int* in_sizes, int n_in,
                              void* d_out, int out_size) {
    const float* x_source = (const float*)d_in[0];
    const float* x_out    = (const float*)d_in[2];
    const float* gs = (const float*)d_in[4];
    const float* bs = (const float*)d_in[5];
    const float* go = (const float*)d_in[6];
    const float* bo = (const float*)d_in[7];
    const float* Wq = (const float*)d_in[8];
    const float* Wk = (const float*)d_in[9];
    const float* Wv = (const float*)d_in[10];
    const float* Wo = (const float*)d_in[11];
    const float* Wp = (const float*)d_in[12];

    float* out   = (float*)d_out;
    float* out_x = out;
    float* out_p = out + (size_t)M_ROWS * H;

    ln_concat_kernel<<<M_ROWS, H>>>(x_source, x_out, gs, bs, go, bo);

    dim3 qkv_grid(M_ROWS / 128, 12);
    qkv_gemm_kernel<<<qkv_grid, 256>>>(Wq, Wk, Wv);

    dim3 agrid(N / 256, HEADS, B);
    attn_kernel<<<agrid, 256>>>();

    dim3 wo_grid(M_ROWS / 128, 4);
    wo_gemm_kernel<<<wo_grid, 256>>>(Wo);

    finish_kernel<<<M_ROWS / 8, 256>>>(x_out, Wp, out_x, out_p);
}

// round 14
// speedup vs baseline: 1.2865x; 1.2865x over previous
#include <cuda_runtime.h>
#include <cuda_fp16.h>
#include <math.h>
#include <stdint.h>

// Problem constants
#define B   16
#define N   1024
#define H   256
#define DS  3
#define HEADS 8
#define DH  32
#define TWO_H 512
#define M_ROWS (B * N)          // 16384
#define EPS 1e-5f
#define SCALE 0.17677669529663687f  // 1/sqrt(32)

// ---------------- scratch (static device globals; no allocation) -------------
__device__ float   g_f  [M_ROWS * TWO_H];
__device__ __half  g_q  [M_ROWS * H];    // pre-scaled by SCALE
__device__ __half  g_k  [M_ROWS * H];
__device__ __half  g_v  [M_ROWS * H];
__device__ float   g_msg[M_ROWS * H];
__device__ float   g_m  [M_ROWS * H];

// ---------------- helpers ------------------------------------------------------
__device__ __forceinline__ uint32_t f2tf32(float f) {
    uint32_t u;
    asm("cvt.rna.tf32.f32 %0, %1;" : "=r"(u) : "f"(f));
    return u;
}

__device__ __forceinline__ uint32_t pack2h(float lo, float hi) {
    uint32_t r;
    asm("cvt.rn.f16x2.f32 %0, %1, %2;" : "=r"(r) : "f"(hi), "f"(lo));
    return r;
}

__device__ __forceinline__ void mma_tf32(float* c,
                                         uint32_t a0, uint32_t a1, uint32_t a2, uint32_t a3,
                                         uint32_t b0, uint32_t b1) {
    asm volatile(
        "mma.sync.aligned.m16n8k8.row.col.f32.tf32.tf32.f32 "
        "{%0,%1,%2,%3}, {%4,%5,%6,%7}, {%8,%9}, {%0,%1,%2,%3};\n"
        : "+f"(c[0]), "+f"(c[1]), "+f"(c[2]), "+f"(c[3])
        : "r"(a0), "r"(a1), "r"(a2), "r"(a3), "r"(b0), "r"(b1));
}

__device__ __forceinline__ void mma_f16(float* c,
                                        uint32_t a0, uint32_t a1, uint32_t a2, uint32_t a3,
                                        uint32_t b0, uint32_t b1) {
    asm volatile(
        "mma.sync.aligned.m16n8k16.row.col.f32.f16.f16.f32 "
        "{%0,%1,%2,%3}, {%4,%5,%6,%7}, {%8,%9}, {%0,%1,%2,%3};\n"
        : "+f"(c[0]), "+f"(c[1]), "+f"(c[2]), "+f"(c[3])
        : "r"(a0), "r"(a1), "r"(a2), "r"(a3), "r"(b0), "r"(b1));
}

// ---------------- kernel 1: dual LayerNorm + concat (one-pass, shfl) ---------
__global__ void ln_concat_kernel(const float* __restrict__ xs,
                                 const float* __restrict__ xo,
                                 const float* __restrict__ gs,
                                 const float* __restrict__ bs,
                                 const float* __restrict__ go,
                                 const float* __restrict__ bo) {
    __shared__ float red[8][4];
    __shared__ float res[4];
    int row = blockIdx.x;
    int t = threadIdx.x;
    int lane = t & 31, warp = t >> 5;

    float v1 = xs[row * H + t];
    float v2 = xo[row * H + t];

    float s1 = v1, q1 = v1 * v1, s2 = v2, q2 = v2 * v2;
    #pragma unroll
    for (int off = 16; off > 0; off >>= 1) {
        s1 += __shfl_xor_sync(0xFFFFFFFFu, s1, off);
        q1 += __shfl_xor_sync(0xFFFFFFFFu, q1, off);
        s2 += __shfl_xor_sync(0xFFFFFFFFu, s2, off);
        q2 += __shfl_xor_sync(0xFFFFFFFFu, q2, off);
    }
    if (lane == 0) {
        red[warp][0] = s1; red[warp][1] = q1;
        red[warp][2] = s2; red[warp][3] = q2;
    }
    __syncthreads();
    if (t < 32) {
        int q = t >> 3, w = t & 7;
        float x = red[w][q];
        x += __shfl_xor_sync(0xFFFFFFFFu, x, 1);
        x += __shfl_xor_sync(0xFFFFFFFFu, x, 2);
        x += __shfl_xor_sync(0xFFFFFFFFu, x, 4);
        if (w == 0) res[q] = x;
    }
    __syncthreads();

    float mean1 = res[0] * (1.0f / H);
    float var1  = res[1] * (1.0f / H) - mean1 * mean1;
    float mean2 = res[2] * (1.0f / H);
    float var2  = res[3] * (1.0f / H) - mean2 * mean2;

    g_f[row * TWO_H + t]     = (v1 - mean1) * rsqrtf(var1 + EPS) * gs[t] + bs[t];
    g_f[row * TWO_H + H + t] = (v2 - mean2) * rsqrtf(var2 + EPS) * go[t] + bo[t];
}

// ---------------- tf32 MMA GEMM core ------------------------------------------
// 128x64 tile, 8 warps (4m x 2n), warp 32x32, BK=32. OUT_F16: f16 store + scale.
template <int OUT_F16>
__device__ __forceinline__ void gemm_mma_body(const float* __restrict__ A,
                                              const float* __restrict__ W,
                                              float* __restrict__ Cf,
                                              __half* __restrict__ Ch,
                                              float out_scale,
                                              int K, int row0, int col0) {
    __shared__ uint32_t As[128][36];
    __shared__ uint32_t Bs[32][72];

    int t = threadIdx.x;
    int w = t >> 5, lane = t & 31;
    int quad = lane >> 2, c = lane & 3;
    int wm = (w & 3) * 32;
    int wn = (w >> 2) * 32;

    float acc[2][4][4];
    #pragma unroll
    for (int mt = 0; mt < 2; mt++)
        #pragma unroll
        for (int nt = 0; nt < 4; nt++)
            #pragma unroll
            for (int i = 0; i < 4; i++) acc[mt][nt][i] = 0.0f;

    int a_row = t >> 1, a_col = (t & 1) * 16;
    int b_row = t >> 3, b_col = (t & 7) * 8;

    for (int k0 = 0; k0 < K; k0 += 32) {
        const float* ap = A + (size_t)(row0 + a_row) * K + k0 + a_col;
        float4 f0 = *(const float4*)(ap + 0);
        float4 f1 = *(const float4*)(ap + 4);
        float4 f2 = *(const float4*)(ap + 8);
        float4 f3 = *(const float4*)(ap + 12);
        uint4 u;
        u.x = f2tf32(f0.x); u.y = f2tf32(f0.y); u.z = f2tf32(f0.z); u.w = f2tf32(f0.w);
        *(uint4*)&As[a_row][a_col + 0] = u;
        u.x = f2tf32(f1.x); u.y = f2tf32(f1.y); u.z = f2tf32(f1.z); u.w = f2tf32(f1.w);
        *(uint4*)&As[a_row][a_col + 4] = u;
        u.x = f2tf32(f2.x); u.y = f2tf32(f2.y); u.z = f2tf32(f2.z); u.w = f2tf32(f2.w);
        *(uint4*)&As[a_row][a_col + 8] = u;
        u.x = f2tf32(f3.x); u.y = f2tf32(f3.y); u.z = f2tf32(f3.z); u.w = f2tf32(f3.w);
        *(uint4*)&As[a_row][a_col + 12] = u;

        const float* bp = W + (size_t)(k0 + b_row) * H + col0 + b_col;
        float4 g0 = *(const float4*)(bp + 0);
        float4 g1 = *(const float4*)(bp + 4);
        u.x = f2tf32(g0.x); u.y = f2tf32(g0.y); u.z = f2tf32(g0.z); u.w = f2tf32(g0.w);
        *(uint4*)&Bs[b_row][b_col + 0] = u;
        u.x = f2tf32(g1.x); u.y = f2tf32(g1.y); u.z = f2tf32(g1.z); u.w = f2tf32(g1.w);
        *(uint4*)&Bs[b_row][b_col + 4] = u;
        __syncthreads();

        #pragma unroll
        for (int ks = 0; ks < 4; ks++) {
            int kk = ks * 8;
            uint32_t a[2][4];
            #pragma unroll
            for (int mt = 0; mt < 2; mt++) {
                int mrow = wm + mt * 16;
                a[mt][0] = As[mrow + quad][kk + c];
                a[mt][1] = As[mrow + quad + 8][kk + c];
                a[mt][2] = As[mrow + quad][kk + c + 4];
                a[mt][3] = As[mrow + quad + 8][kk + c + 4];
            }
            #pragma unroll
            for (int nt = 0; nt < 4; nt++) {
                uint32_t b0 = Bs[kk + c][wn + nt * 8 + quad];
                uint32_t b1 = Bs[kk + c + 4][wn + nt * 8 + quad];
                #pragma unroll
                for (int mt = 0; mt < 2; mt++)
                    mma_tf32(acc[mt][nt], a[mt][0], a[mt][1], a[mt][2], a[mt][3], b0, b1);
            }
        }
        __syncthreads();
    }

    #pragma unroll
    for (int mt = 0; mt < 2; mt++) {
        int row = row0 + wm + mt * 16 + quad;
        #pragma unroll
        for (int nt = 0; nt < 4; nt++) {
            int col = col0 + wn + nt * 8 + 2 * c;
            if (OUT_F16) {
                *(uint32_t*)&Ch[(size_t)row * H + col] =
                    pack2h(acc[mt][nt][0] * out_scale, acc[mt][nt][1] * out_scale);
                *(uint32_t*)&Ch[(size_t)(row + 8) * H + col] =
                    pack2h(acc[mt][nt][2] * out_scale, acc[mt][nt][3] * out_scale);
            } else {
                *(float2*)&Cf[(size_t)row * H + col] = make_float2(acc[mt][nt][0], acc[mt][nt][1]);
                *(float2*)&Cf[(size_t)(row + 8) * H + col] = make_float2(acc[mt][nt][2], acc[mt][nt][3]);
            }
        }
    }
}

__global__ void __launch_bounds__(256)
qkv_gemm_kernel(const float* __restrict__ Wq,
                const float* __restrict__ Wk,
                const float* __restrict__ Wv) {
    int sel = blockIdx.y >> 2;
    const float* W = (sel == 0) ? Wq : (sel == 1) ? Wk : Wv;
    __half* C = (sel == 0) ? g_q : (sel == 1) ? g_k : g_v;
    float scale = (sel == 0) ? SCALE : 1.0f;
    gemm_mma_body<1>(g_f, W, nullptr, C, scale, TWO_H, blockIdx.x * 128, (blockIdx.y & 3) * 64);
}

__global__ void __launch_bounds__(256)
wo_gemm_kernel(const float* __restrict__ Wo) {
    gemm_mma_body<0>(g_msg, Wo, g_m, nullptr, 1.0f, H, blockIdx.x * 128, blockIdx.y * 64);
}

// ---------------- attention (f16 mma m16n8k16, no-max softmax) -----------------
// grid (N/256, HEADS, B), 256 threads = 8 warps; warp w -> 32 q rows (2 m-tiles)
#define KS_PITCH 40    // f16 elems per Ks row (32 + 8 pad): conflict-free frags
#define VT_PITCH 136   // f16 elems per Vt row (128 + 8 pad)

__global__ void __launch_bounds__(256)
attn_kernel() {
    __shared__ __align__(16) uint16_t Ks[128 * KS_PITCH];   // [j][d] f16
    __shared__ __align__(16) uint16_t Vt[32 * VT_PITCH];    // [d][j] f16

    int b = blockIdx.z;
    int h = blockIdx.y;
    int q0 = blockIdx.x * 256;
    int t = threadIdx.x;
    int w = t >> 5, lane = t & 31;
    int quad = lane >> 2;
    int c    = lane & 3;

    // Q fragments for 2 m-tiles: m16n8k16 A layout, q pre-scaled f16
    uint32_t qa[2][2][4];
    #pragma unroll
    for (int mt = 0; mt < 2; mt++) {
        const __half* qb  = g_q + (size_t)(b * N + q0 + w * 32 + mt * 16 + quad) * H + h * DH;
        const __half* qb8 = qb + 8 * H;
        #pragma unroll
        for (int ks = 0; ks < 2; ks++) {
            qa[mt][ks][0] = *(const uint32_t*)&qb [ks * 16 + 2 * c];
            qa[mt][ks][1] = *(const uint32_t*)&qb8[ks * 16 + 2 * c];
            qa[mt][ks][2] = *(const uint32_t*)&qb [ks * 16 + 2 * c + 8];
            qa[mt][ks][3] = *(const uint32_t*)&qb8[ks * 16 + 2 * c + 8];
        }
    }

    float o[2][4][4];
    #pragma unroll
    for (int mt = 0; mt < 2; mt++)
        #pragma unroll
        for (int nt = 0; nt < 4; nt++)
            #pragma unroll
            for (int i = 0; i < 4; i++) o[mt][nt][i] = 0.0f;
    float lsum[2][2] = {{0.0f, 0.0f}, {0.0f, 0.0f}};

    bool evenj = ((t & 8) == 0);

    for (int j0t = 0; j0t < N; j0t += 128) {
        // K tile: [j][d] direct copy, uint4 = 8 f16
        #pragma unroll
        for (int it = 0; it < 2; it++) {
            int idx = it * 256 + t;
            int j  = idx >> 2;
            int d8 = (idx & 3) * 8;
            *(uint4*)&Ks[j * KS_PITCH + d8] =
                *(const uint4*)&g_k[(size_t)(b * N + j0t + j) * H + h * DH + d8];
        }
        // V tile: transpose into Vt[d][j] via xor-8 pairing, 4B stores
        #pragma unroll
        for (int it = 0; it < 4; it++) {
            int idx = it * 256 + t;
            int j  = idx >> 3;
            int d4 = (idx & 7) * 4;
            uint2 u = *(const uint2*)&g_v[(size_t)(b * N + j0t + j) * H + h * DH + d4];
            uint32_t olo = __shfl_xor_sync(0xFFFFFFFFu, u.x, 8);
            uint32_t ohi = __shfl_xor_sync(0xFFFFFFFFu, u.y, 8);
            int jb = j & ~1;
            if (evenj) {
                uint32_t p0 = (u.x & 0xffffu) | (olo << 16);
                uint32_t p1 = (u.x >> 16)    | (olo & 0xffff0000u);
                *(uint32_t*)&Vt[(d4 + 0) * VT_PITCH + jb] = p0;
                *(uint32_t*)&Vt[(d4 + 1) * VT_PITCH + jb] = p1;
            } else {
                uint32_t p2 = (ohi & 0xffffu) | (u.y << 16);
                uint32_t p3 = (ohi >> 16)     | (u.y & 0xffff0000u);
                *(uint32_t*)&Vt[(d4 + 2) * VT_PITCH + jb] = p2;
                *(uint32_t*)&Vt[(d4 + 3) * VT_PITCH + jb] = p3;
            }
        }
        __syncthreads();

        #pragma unroll 2
        for (int g = 0; g < 8; g++) {
            int j0 = g * 16;
            float slo[2][4] = {{0,0,0,0},{0,0,0,0}};
            float shi[2][4] = {{0,0,0,0},{0,0,0,0}};
            #pragma unroll
            for (int ks = 0; ks < 2; ks++) {
                const uint16_t* krl = &Ks[(j0 + quad) * KS_PITCH + ks * 16 + 2 * c];
                const uint16_t* krh = krl + 8 * KS_PITCH;
                uint32_t bl0 = *(const uint32_t*)(krl);
                uint32_t bl1 = *(const uint32_t*)(krl + 8);
                uint32_t bh0 = *(const uint32_t*)(krh);
                uint32_t bh1 = *(const uint32_t*)(krh + 8);
                #pragma unroll
                for (int mt = 0; mt < 2; mt++) {
                    mma_f16(slo[mt], qa[mt][ks][0], qa[mt][ks][1], qa[mt][ks][2], qa[mt][ks][3], bl0, bl1);
                    mma_f16(shi[mt], qa[mt][ks][0], qa[mt][ks][1], qa[mt][ks][2], qa[mt][ks][3], bh0, bh1);
                }
            }
            // exp + pack: S C-layout == PV A-layout (f16x2) — no shuffles
            uint32_t pa[2][4];
            #pragma unroll
            for (int mt = 0; mt < 2; mt++) {
                float e0 = __expf(slo[mt][0]), e1 = __expf(slo[mt][1]);
                float e2 = __expf(slo[mt][2]), e3 = __expf(slo[mt][3]);
                float f0 = __expf(shi[mt][0]), f1 = __expf(shi[mt][1]);
                float f2 = __expf(shi[mt][2]), f3 = __expf(shi[mt][3]);
                lsum[mt][0] += e0 + e1 + f0 + f1;
                lsum[mt][1] += e2 + e3 + f2 + f3;
                pa[mt][0] = pack2h(e0, e1);
                pa[mt][1] = pack2h(e2, e3);
                pa[mt][2] = pack2h(f0, f1);
                pa[mt][3] = pack2h(f2, f3);
            }
            #pragma unroll
            for (int nt = 0; nt < 4; nt++) {
                const uint16_t* vr = &Vt[(nt * 8 + quad) * VT_PITCH + j0 + 2 * c];
                uint32_t b0 = *(const uint32_t*)(vr);
                uint32_t b1 = *(const uint32_t*)(vr + 8);
                mma_f16(o[0][nt], pa[0][0], pa[0][1], pa[0][2], pa[0][3], b0, b1);
                mma_f16(o[1][nt], pa[1][0], pa[1][1], pa[1][2], pa[1][3], b0, b1);
            }
        }
        __syncthreads();
    }

    #pragma unroll
    for (int mt = 0; mt < 2; mt++) {
        float l0 = lsum[mt][0], l1 = lsum[mt][1];
        l0 += __shfl_xor_sync(0xFFFFFFFFu, l0, 1);
        l0 += __shfl_xor_sync(0xFFFFFFFFu, l0, 2);
        l1 += __shfl_xor_sync(0xFFFFFFFFu, l1, 1);
        l1 += __shfl_xor_sync(0xFFFFFFFFu, l1, 2);
        float inv0 = 1.0f / l0, inv1 = 1.0f / l1;

        float* ob  = g_msg + (size_t)(b * N + q0 + w * 32 + mt * 16 + quad) * H + h * DH;
        float* ob8 = ob + 8 * H;
        #pragma unroll
        for (int nt = 0; nt < 4; nt++) {
            int col = nt * 8 + 2 * c;
            *(float2*)&ob [col] = make_float2(o[mt][nt][0] * inv0, o[mt][nt][1] * inv0);
            *(float2*)&ob8[col] = make_float2(o[mt][nt][2] * inv1, o[mt][nt][3] * inv1);
        }
    }
}

// ---------------- kernel 5: residual + position head -------------------------
__global__ void finish_kernel(const float* __restrict__ x_out,
                              const float* __restrict__ Wp,
                              float* __restrict__ out_x,
                              float* __restrict__ out_p) {
    int warp = threadIdx.x >> 5;
    int lane = threadIdx.x & 31;
    int row = blockIdx.x * 8 + warp;

    const float* mr = g_m + (size_t)row * H;
    float p0 = 0.0f, p1 = 0.0f, p2 = 0.0f;
    #pragma unroll
    for (int c = lane; c < H; c += 32) {
        float mv = mr[c];
        out_x[(size_t)row * H + c] = x_out[(size_t)row * H + c] + mv;
        p0 += mv * Wp[c * DS + 0];
        p1 += mv * Wp[c * DS + 1];
        p2 += mv * Wp[c * DS + 2];
    }
    #pragma unroll
    for (int off = 16; off > 0; off >>= 1) {
        p0 += __shfl_xor_sync(0xFFFFFFFF, p0, off);
        p1 += __shfl_xor_sync(0xFFFFFFFF, p1, off);
        p2 += __shfl_xor_sync(0xFFFFFFFF, p2, off);
    }
    if (lane == 0) {
        out_p[(size_t)row * DS + 0] = p0;
        out_p[(size_t)row * DS + 1] = p1;
        out_p[(size_t)row * DS + 2] = p2;
    }
}

// ---------------- launcher ----------------------------------------------------
extern "C" void kernel_launch(void* const* d_in, const int* in_sizes, int n_in,
                              void* d_out, int out_size) {
    const float* x_source = (const float*)d_in[0];
    const float* x_out    = (const float*)d_in[2];
    const float* gs = (const float*)d_in[4];
    const float* bs = (const float*)d_in[5];
    const float* go = (const float*)d_in[6];
    const float* bo = (const float*)d_in[7];
    const float* Wq = (const float*)d_in[8];
    const float* Wk = (const float*)d_in[9];
    const float* Wv = (const float*)d_in[10];
    const float* Wo = (const float*)d_in[11];
    const float* Wp = (const float*)d_in[12];

    float* out   = (float*)d_out;
    float* out_x = out;
    float* out_p = out + (size_t)M_ROWS * H;

    ln_concat_kernel<<<M_ROWS, H>>>(x_source, x_out, gs, bs, go, bo);

    dim3 qkv_grid(M_ROWS / 128, 12);
    qkv_gemm_kernel<<<qkv_grid, 256>>>(Wq, Wk, Wv);

    dim3 agrid(N / 256, HEADS, B);
    attn_kernel<<<agrid, 256>>>();

    dim3 wo_grid(M_ROWS / 128, 4);
    wo_gemm_kernel<<<wo_grid, 4 * 64>>>(Wo);

    finish_kernel<<<M_ROWS / 8, 256>>>(x_out, Wp, out_x, out_p);
}